// round 15
// baseline (speedup 1.0000x reference)
#include <cuda_runtime.h>
#include <cuda_bf16.h>
#include <cstdint>

// Scratch (static device globals — no allocation).
__device__ uint4 g_Tb4[4][32][1024];      // 2 MB: bf16 pose-chunk partials of T[b][g]
__device__ float g_pp[64][2048];          // 512 KB: stage2 partial pooled
__device__ int   g_ctr  = 0;              // grid-arrival counter (self-resetting)
__device__ int   g_ctr2 = 0;

// ---- packed f32x2 helpers ----
__device__ __forceinline__ unsigned long long pack2(float x, float y) {
    unsigned long long r;
    asm("mov.b64 %0, {%1,%2};" : "=l"(r) : "f"(x), "f"(y));
    return r;
}
__device__ __forceinline__ void fma2(unsigned long long& d, unsigned long long a, unsigned long long b) {
    asm("fma.rn.f32x2 %0, %1, %2, %0;" : "+l"(d) : "l"(a), "l"(b));
}
__device__ __forceinline__ float2 unpk(unsigned long long v) {
    float2 r;
    asm("mov.b64 {%0,%1}, %2;" : "=f"(r.x), "=f"(r.y) : "l"(v));
    return r;
}
// d[31:16] = bf16(hi), d[15:0] = bf16(lo)
__device__ __forceinline__ uint32_t bfpack(float hi, float lo) {
    uint32_t r;
    asm("cvt.rn.bf16x2.f32 %0, %1, %2;" : "=r"(r) : "f"(hi), "f"(lo));
    return r;
}

// ============================================================================
// Stage 1 (R8 config: warp-autonomous, 4 batches/warp, 16 poses/warp):
//   T[b, j*64 + r*8 + x] += (CP[b,i] @ Wc[i])[r][x],  i = pose*128 + j.
// 1024 warps in 512 blocks of 64 thr: bq = gw&7, jg = (gw>>3)&31, sc = gw>>8.
// Lane l owns row r=l&7 of matrix q=l>>3 for 4 b's. W staged per-warp in
// bank-skewed smem, double-buffered, __syncwarp only. Tpart stored bf16.
// ============================================================================
__global__ void __launch_bounds__(64) k_stage1(const float* __restrict__ cp,
                                               const float* __restrict__ wc) {
    const int tid = threadIdx.x;
    const int wip = tid >> 5;
    const int l   = tid & 31;
    const int gw  = blockIdx.x * 2 + wip;   // 0..1023
    const int bq  = gw & 7;
    const int jg  = (gw >> 3) & 31;
    const int sc  = gw >> 8;                // 0..3
    const int b0  = bq * 4;
    const int j0  = jg * 4;
    const int p0  = sc * 16;
    const int q   = l >> 3;

    __shared__ float sW[2][2][288];   // [warp][buf][4*72]

    const int f0 = l, f1 = l + 32;
    const int so0 = (f0 >> 4) * 72 + ((f0 & 15) >> 1) * 8 + (f0 & 1) * 4;
    const int so1 = (f1 >> 4) * 72 + ((f1 & 15) >> 1) * 8 + (f1 & 1) * 4;

    const float4* ap[4];
#pragma unroll
    for (int bb = 0; bb < 4; ++bb)
        ap[bb] = reinterpret_cast<const float4*>(cp)
                 + ((size_t)(b0 + bb) * 8192 + (size_t)p0 * 128 + j0) * 16;
    const float4* wp = reinterpret_cast<const float4*>(wc)
                       + ((size_t)p0 * 128 + j0) * 16;

    float4 A[2][4][2];
    float4 Wr[2][2];
#pragma unroll
    for (int bb = 0; bb < 4; ++bb) {
        A[0][bb][0] = ap[bb][2 * l];
        A[0][bb][1] = ap[bb][2 * l + 1];
    }
    Wr[0][0] = wp[f0]; Wr[0][1] = wp[f1];

    unsigned long long acc[4][4];
#pragma unroll
    for (int bb = 0; bb < 4; ++bb)
#pragma unroll
        for (int c = 0; c < 4; ++c) acc[bb][c] = 0ull;

#pragma unroll 2
    for (int it = 0; it < 16; ++it) {
        const int cur = it & 1, nxt = cur ^ 1;
        float* sw = sW[wip][cur];
        *reinterpret_cast<float4*>(sw + so0) = Wr[cur][0];
        *reinterpret_cast<float4*>(sw + so1) = Wr[cur][1];
        __syncwarp();

        if (it < 15) {
#pragma unroll
            for (int bb = 0; bb < 4; ++bb) {
                ap[bb] += 2048;
                A[nxt][bb][0] = ap[bb][2 * l];
                A[nxt][bb][1] = ap[bb][2 * l + 1];
            }
            wp += 2048;
            Wr[nxt][0] = wp[f0]; Wr[nxt][1] = wp[f1];
        }

        float am[4][8];
#pragma unroll
        for (int bb = 0; bb < 4; ++bb) {
            am[bb][0] = A[cur][bb][0].x; am[bb][1] = A[cur][bb][0].y;
            am[bb][2] = A[cur][bb][0].z; am[bb][3] = A[cur][bb][0].w;
            am[bb][4] = A[cur][bb][1].x; am[bb][5] = A[cur][bb][1].y;
            am[bb][6] = A[cur][bb][1].z; am[bb][7] = A[cur][bb][1].w;
        }
        const float* wq = sw + q * 72;
#pragma unroll
        for (int m = 0; m < 8; ++m) {
            const ulonglong2 wlo = *reinterpret_cast<const ulonglong2*>(wq + m * 8);
            const ulonglong2 whi = *reinterpret_cast<const ulonglong2*>(wq + m * 8 + 4);
#pragma unroll
            for (int bb = 0; bb < 4; ++bb) {
                const unsigned long long pa = pack2(am[bb][m], am[bb][m]);
                fma2(acc[bb][0], pa, wlo.x); fma2(acc[bb][1], pa, wlo.y);
                fma2(acc[bb][2], pa, whi.x); fma2(acc[bb][3], pa, whi.y);
            }
        }
        __syncwarp();
    }

    // Lane writes its 8 T values (g = j0*64 + l*8 ..+8) per b as 8 bf16 = 16B.
#pragma unroll
    for (int bb = 0; bb < 4; ++bb) {
        float2 v0 = unpk(acc[bb][0]), v1 = unpk(acc[bb][1]);
        float2 v2 = unpk(acc[bb][2]), v3 = unpk(acc[bb][3]);
        uint4 u;
        u.x = bfpack(v0.y, v0.x);
        u.y = bfpack(v1.y, v1.x);
        u.z = bfpack(v2.y, v2.x);
        u.w = bfpack(v3.y, v3.x);
        g_Tb4[sc][b0 + bb][jg * 32 + l] = u;   // uint4 idx = (j0*64 + l*8)/8
    }
}

// ============================================================================
// Stage 2 + final (fused): 64 blocks x 256 threads, single wave.
// Block owns 128 g: fold 4 bf16 pose-chunk partials -> sT; E folded over
// hid%64 at load; per-gq partials folded -> g_pp[blk]. Then grid-arrival
// counter (BOUNDED spin: bound unreachable in practice; if ever hit, the
// run produces a wrong answer -> visible rel_err failure, never a hang);
// after all 64 blocks arrive, block computes final output for b = blk&31
// (o-half = blk>>5): pooled = sum 64 slots / 64 + rel,
// out[b,o] = pooled(8x8) @ w_next[o]. Deterministic (no fp atomics).
// ============================================================================
__global__ void __launch_bounds__(256) k_stage2(const float* __restrict__ E,
                                                const float* __restrict__ wn,
                                                const float* __restrict__ rel,
                                                float* __restrict__ out) {
    const int blk = blockIdx.x;
    const int g0  = blk * 128;
    const int tid = threadIdx.x;

    __shared__ float buf[8192];     // phase A: sT[128][34]; phase B: sF[4][2048]; tail: wn
    __shared__ float sP[4][64];
    __shared__ float sN[64];

    // ---- load + fold bf16 Tpart into sT (buf[gg*34 + b]) ----
    {
        const uint32_t* tb = reinterpret_cast<const uint32_t*>(g_Tb4);
        const int gh = g0 >> 1;     // u32 offset within a b-row
#pragma unroll
        for (int k = 0; k < 8; ++k) {
            const int p = k * 256 + tid;       // 0..2047
            const int b = p >> 6, gp = p & 63; // gp: u32 pair index (2 g's)
            float lo = 0.f, hi = 0.f;
#pragma unroll
            for (int pc = 0; pc < 4; ++pc) {
                const uint32_t u = tb[(size_t)(pc * 32 + b) * 4096 + gh + gp];
                const __nv_bfloat162 h = *reinterpret_cast<const __nv_bfloat162*>(&u);
                lo += __low2float(h);
                hi += __high2float(h);
            }
            buf[(2 * gp) * 34 + b]     = lo;
            buf[(2 * gp + 1) * 34 + b] = hi;
        }
    }
    __syncthreads();

    const int c  = tid & 63;
    const int gq = tid >> 6;
    unsigned long long acc[16];
#pragma unroll
    for (int i = 0; i < 16; ++i) acc[i] = 0ull;

    const float* Eb = E + (size_t)g0 * 256 + c;
#pragma unroll 2
    for (int t = 0; t < 32; ++t) {
        const int gg = gq * 32 + t;
        const float* er = Eb + (size_t)gg * 256;
        const float ev = er[0] + er[64] + er[128] + er[192];
        const unsigned long long ep = pack2(ev, ev);
        const unsigned long long* t2 =
            reinterpret_cast<const unsigned long long*>(&buf[gg * 34]);
#pragma unroll
        for (int bb = 0; bb < 16; ++bb) fma2(acc[bb], t2[bb], ep);
    }
    __syncthreads();   // done reading sT; buf reused for sF

    // ---- spill per-gq partials, fold, write ONE g_pp slot ----
#pragma unroll
    for (int bb = 0; bb < 16; ++bb) {
        float2 v = unpk(acc[bb]);
        buf[gq * 2048 + (2 * bb + 0) * 64 + c] = v.x;
        buf[gq * 2048 + (2 * bb + 1) * 64 + c] = v.y;
    }
    __syncthreads();

    float* dst = g_pp[blk];
#pragma unroll
    for (int k = 0; k < 8; ++k) {
        const int e = k * 256 + tid;
        dst[e] = buf[e] + buf[2048 + e] + buf[4096 + e] + buf[6144 + e];
    }

    // ---- grid arrival + BOUNDED wait (64 blocks <= 148 SMs: single wave) ----
    __threadfence();
    __syncthreads();
    if (tid == 0) {
        atomicAdd(&g_ctr, 1);
        int spins = 0;
        while (atomicAdd(&g_ctr, 0) < 64 && spins < (1 << 22)) {
            __nanosleep(100);
            ++spins;
        }
    }
    __syncthreads();
    __threadfence();

    // ---- final: block handles b = blk&31, o-half = blk>>5 ----
    const int b    = blk & 31;
    const int half = blk >> 5;

    float s = 0.f;
#pragma unroll 4
    for (int k = 0; k < 16; ++k) s += g_pp[gq * 16 + k][b * 64 + c];
    sP[gq][c] = s;

    {
        float4* s4 = reinterpret_cast<float4*>(buf);
        const float4* w4 = reinterpret_cast<const float4*>(wn);
#pragma unroll
        for (int k = 0; k < 4; ++k) s4[k * 256 + tid] = w4[k * 256 + tid];
    }
    __syncthreads();
    if (tid < 64) {
        sN[tid] = (sP[0][tid] + sP[1][tid] + sP[2][tid] + sP[3][tid]) * (1.f / 64.f)
                  + rel[tid];
    }
    __syncthreads();

    const int r = c >> 3, col = c & 7;
    float a[8];
#pragma unroll
    for (int m = 0; m < 8; ++m) a[m] = sN[r * 8 + m];
    float* ob = out + (size_t)b * 4096;
#pragma unroll
    for (int t = 0; t < 8; ++t) {
        const int o = half * 32 + gq * 8 + t;
        float accv = 0.f;
#pragma unroll
        for (int m = 0; m < 8; ++m) accv += a[m] * buf[o * 64 + m * 8 + col];
        ob[o * 64 + c] = accv;
    }

    // ---- self-reset counters for next graph replay ----
    if (tid == 0) {
        const int r2 = atomicAdd(&g_ctr2, 1);
        if (r2 == 63) {
            g_ctr  = 0;
            g_ctr2 = 0;
            __threadfence();
        }
    }
}

extern "C" void kernel_launch(void* const* d_in, const int* in_sizes, int n_in,
                              void* d_out, int out_size) {
    const float* cp  = (const float*)d_in[0];  // current_pose (32,8192,64)
    const float* wc  = (const float*)d_in[1];  // w_current    (8192,8,8)
    const float* wn  = (const float*)d_in[2];  // w_next       (64,8,8)
    const float* E   = (const float*)d_in[3];  // E_proj       (32,256,256)
    const float* rel = (const float*)d_in[4];  // rel_embedd   (64)
    float* out = (float*)d_out;                // (32,64,64) fp32

    k_stage1<<<512, 64>>>(cp, wc);
    k_stage2<<<64, 256>>>(E, wn, rel, out);
}

// round 16
// speedup vs baseline: 1.4672x; 1.4672x over previous
#include <cuda_runtime.h>
#include <cuda_bf16.h>
#include <cstdint>

// Scratch (static device globals — no allocation).
__device__ uint4 g_Tb4[4][32][1024];      // 2 MB: bf16 pose-chunk partials of T[b][g]
__device__ float g_pp[128][2048];         // 1 MB: stage2 partial pooled [slot][b*64+c]

// ---- packed f32x2 helpers ----
__device__ __forceinline__ unsigned long long pack2(float x, float y) {
    unsigned long long r;
    asm("mov.b64 %0, {%1,%2};" : "=l"(r) : "f"(x), "f"(y));
    return r;
}
__device__ __forceinline__ void fma2(unsigned long long& d, unsigned long long a, unsigned long long b) {
    asm("fma.rn.f32x2 %0, %1, %2, %0;" : "+l"(d) : "l"(a), "l"(b));
}
__device__ __forceinline__ float2 unpk(unsigned long long v) {
    float2 r;
    asm("mov.b64 {%0,%1}, %2;" : "=f"(r.x), "=f"(r.y) : "l"(v));
    return r;
}
// d[31:16] = bf16(hi), d[15:0] = bf16(lo)
__device__ __forceinline__ uint32_t bfpack(float hi, float lo) {
    uint32_t r;
    asm("cvt.rn.bf16x2.f32 %0, %1, %2;" : "=r"(r) : "f"(hi), "f"(lo));
    return r;
}

// ============================================================================
// Stage 1 (proven R8 config: warp-autonomous, 4 batches/warp, 16 poses/warp):
//   T[b, j*64 + r*8 + x] += (CP[b,i] @ Wc[i])[r][x],  i = pose*128 + j.
// 1024 warps in 512 blocks of 64 thr: bq = gw&7, jg = (gw>>3)&31, sc = gw>>8.
// Lane l owns row r=l&7 of matrix q=l>>3 for 4 b's. W staged per-warp in
// bank-skewed smem, double-buffered, __syncwarp only. Tpart stored bf16.
// ============================================================================
__global__ void __launch_bounds__(64) k_stage1(const float* __restrict__ cp,
                                               const float* __restrict__ wc) {
    const int tid = threadIdx.x;
    const int wip = tid >> 5;
    const int l   = tid & 31;
    const int gw  = blockIdx.x * 2 + wip;   // 0..1023
    const int bq  = gw & 7;
    const int jg  = (gw >> 3) & 31;
    const int sc  = gw >> 8;                // 0..3
    const int b0  = bq * 4;
    const int j0  = jg * 4;
    const int p0  = sc * 16;
    const int q   = l >> 3;

    __shared__ float sW[2][2][288];   // [warp][buf][4*72]

    const int f0 = l, f1 = l + 32;
    const int so0 = (f0 >> 4) * 72 + ((f0 & 15) >> 1) * 8 + (f0 & 1) * 4;
    const int so1 = (f1 >> 4) * 72 + ((f1 & 15) >> 1) * 8 + (f1 & 1) * 4;

    const float4* ap[4];
#pragma unroll
    for (int bb = 0; bb < 4; ++bb)
        ap[bb] = reinterpret_cast<const float4*>(cp)
                 + ((size_t)(b0 + bb) * 8192 + (size_t)p0 * 128 + j0) * 16;
    const float4* wp = reinterpret_cast<const float4*>(wc)
                       + ((size_t)p0 * 128 + j0) * 16;

    float4 A[2][4][2];
    float4 Wr[2][2];
#pragma unroll
    for (int bb = 0; bb < 4; ++bb) {
        A[0][bb][0] = ap[bb][2 * l];
        A[0][bb][1] = ap[bb][2 * l + 1];
    }
    Wr[0][0] = wp[f0]; Wr[0][1] = wp[f1];

    unsigned long long acc[4][4];
#pragma unroll
    for (int bb = 0; bb < 4; ++bb)
#pragma unroll
        for (int c = 0; c < 4; ++c) acc[bb][c] = 0ull;

#pragma unroll 2
    for (int it = 0; it < 16; ++it) {
        const int cur = it & 1, nxt = cur ^ 1;
        float* sw = sW[wip][cur];
        *reinterpret_cast<float4*>(sw + so0) = Wr[cur][0];
        *reinterpret_cast<float4*>(sw + so1) = Wr[cur][1];
        __syncwarp();

        if (it < 15) {
#pragma unroll
            for (int bb = 0; bb < 4; ++bb) {
                ap[bb] += 2048;
                A[nxt][bb][0] = ap[bb][2 * l];
                A[nxt][bb][1] = ap[bb][2 * l + 1];
            }
            wp += 2048;
            Wr[nxt][0] = wp[f0]; Wr[nxt][1] = wp[f1];
        }

        float am[4][8];
#pragma unroll
        for (int bb = 0; bb < 4; ++bb) {
            am[bb][0] = A[cur][bb][0].x; am[bb][1] = A[cur][bb][0].y;
            am[bb][2] = A[cur][bb][0].z; am[bb][3] = A[cur][bb][0].w;
            am[bb][4] = A[cur][bb][1].x; am[bb][5] = A[cur][bb][1].y;
            am[bb][6] = A[cur][bb][1].z; am[bb][7] = A[cur][bb][1].w;
        }
        const float* wq = sw + q * 72;
#pragma unroll
        for (int m = 0; m < 8; ++m) {
            const ulonglong2 wlo = *reinterpret_cast<const ulonglong2*>(wq + m * 8);
            const ulonglong2 whi = *reinterpret_cast<const ulonglong2*>(wq + m * 8 + 4);
#pragma unroll
            for (int bb = 0; bb < 4; ++bb) {
                const unsigned long long pa = pack2(am[bb][m], am[bb][m]);
                fma2(acc[bb][0], pa, wlo.x); fma2(acc[bb][1], pa, wlo.y);
                fma2(acc[bb][2], pa, whi.x); fma2(acc[bb][3], pa, whi.y);
            }
        }
        __syncwarp();
    }

    // Lane writes its 8 T values (g = j0*64 + l*8 ..+8) per b as 8 bf16 = 16B.
#pragma unroll
    for (int bb = 0; bb < 4; ++bb) {
        float2 v0 = unpk(acc[bb][0]), v1 = unpk(acc[bb][1]);
        float2 v2 = unpk(acc[bb][2]), v3 = unpk(acc[bb][3]);
        uint4 u;
        u.x = bfpack(v0.y, v0.x);
        u.y = bfpack(v1.y, v1.x);
        u.z = bfpack(v2.y, v2.x);
        u.w = bfpack(v3.y, v3.x);
        g_Tb4[sc][b0 + bb][jg * 32 + l] = u;   // uint4 idx = (j0*64 + l*8)/8
    }
}

// ============================================================================
// Stage 2 (proven R8 structure): fold 4 bf16 pose-chunk partials of T;
// E folded over hid%64 at load:
//   pp[b,c] += T[b,g] * (E[g][c] + E[g][c+64] + E[g][c+128] + E[g][c+192])
// 128 blocks x 256 threads; block owns 64 g; thread = (c 64, gq 4) x 16 g.
// gq-partials folded in-block through smem -> ONE g_pp slot per block.
// ============================================================================
__global__ void __launch_bounds__(256) k_stage2(const float* __restrict__ E) {
    const int blk = blockIdx.x;
    const int g0  = blk * 64;
    const int tid = threadIdx.x;
    __shared__ float sT[64][34];
    __shared__ float sF[4][2048];

    // ---- load + fold bf16 Tpart into sT[gg][b] ----
    {
        const uint32_t* tb = reinterpret_cast<const uint32_t*>(g_Tb4);
        const int gh = blk * 32;           // u32 offset within a b-row
#pragma unroll
        for (int k = 0; k < 4; ++k) {
            const int p = k * 256 + tid;   // 0..1023
            const int b = p >> 5, gp = p & 31;
            float lo = 0.f, hi = 0.f;
#pragma unroll
            for (int pc = 0; pc < 4; ++pc) {
                const uint32_t u = tb[(size_t)(pc * 32 + b) * 4096 + gh + gp];
                const __nv_bfloat162 h = *reinterpret_cast<const __nv_bfloat162*>(&u);
                lo += __low2float(h);
                hi += __high2float(h);
            }
            sT[2 * gp][b]     = lo;
            sT[2 * gp + 1][b] = hi;
        }
    }
    __syncthreads();

    const int c  = tid & 63;
    const int gq = tid >> 6;
    unsigned long long acc[16];
#pragma unroll
    for (int i = 0; i < 16; ++i) acc[i] = 0ull;

    const float* Eb = E + (size_t)g0 * 256 + c;
#pragma unroll 2
    for (int t = 0; t < 16; ++t) {
        const int gg = gq * 16 + t;
        const float* er = Eb + (size_t)gg * 256;
        const float ev = er[0] + er[64] + er[128] + er[192];
        const unsigned long long ep = pack2(ev, ev);
        const unsigned long long* t2 =
            reinterpret_cast<const unsigned long long*>(&sT[gg][0]);
#pragma unroll
        for (int bb = 0; bb < 16; ++bb) fma2(acc[bb], t2[bb], ep);
    }

    // Spill per-gq partials (lane-consecutive c -> conflict-free).
#pragma unroll
    for (int bb = 0; bb < 16; ++bb) {
        float2 v = unpk(acc[bb]);
        sF[gq][(2 * bb + 0) * 64 + c] = v.x;
        sF[gq][(2 * bb + 1) * 64 + c] = v.y;
    }
    __syncthreads();

    // Fold gq and write ONE slot for this block.
    float* dst = g_pp[blk];
#pragma unroll
    for (int k = 0; k < 8; ++k) {
        const int e = k * 256 + tid;
        dst[e] = sF[0][e] + sF[1][e] + sF[2][e] + sF[3][e];
    }
}

// ============================================================================
// Final (proven R8): pooled[b,c] = (sum of 128 slots)/64 + rel[c];
//        out[b,o] = pooled(8x8) @ w_next[o].   32 blocks x 256 threads.
// ============================================================================
__global__ void __launch_bounds__(256) k_final(const float* __restrict__ wn,
                                               const float* __restrict__ rel,
                                               float* __restrict__ out) {
    const int b   = blockIdx.x;
    const int tid = threadIdx.x;
    const int c   = tid & 63, qd = tid >> 6;
    __shared__ float sN[64];
    __shared__ float sP[4][64];
    __shared__ float sWn[4096];

    float s = 0.f;
#pragma unroll 8
    for (int k = 0; k < 32; ++k) s += g_pp[qd * 32 + k][b * 64 + c];
    sP[qd][c] = s;

    {
        float4* s4 = reinterpret_cast<float4*>(sWn);
        const float4* w4 = reinterpret_cast<const float4*>(wn);
#pragma unroll
        for (int k = 0; k < 4; ++k) s4[k * 256 + tid] = w4[k * 256 + tid];
    }
    __syncthreads();
    if (tid < 64) {
        sN[tid] = (sP[0][tid] + sP[1][tid] + sP[2][tid] + sP[3][tid]) * (1.f / 64.f)
                  + rel[tid];
    }
    __syncthreads();

    const int r = c >> 3, col = c & 7;
    float a[8];
#pragma unroll
    for (int m = 0; m < 8; ++m) a[m] = sN[r * 8 + m];
    float* ob = out + (size_t)b * 4096;
#pragma unroll 4
    for (int o = qd * 16; o < qd * 16 + 16; ++o) {
        float accv = 0.f;
#pragma unroll
        for (int m = 0; m < 8; ++m) accv += a[m] * sWn[o * 64 + m * 8 + col];
        ob[o * 64 + c] = accv;
    }
}

extern "C" void kernel_launch(void* const* d_in, const int* in_sizes, int n_in,
                              void* d_out, int out_size) {
    const float* cp  = (const float*)d_in[0];  // current_pose (32,8192,64)
    const float* wc  = (const float*)d_in[1];  // w_current    (8192,8,8)
    const float* wn  = (const float*)d_in[2];  // w_next       (64,8,8)
    const float* E   = (const float*)d_in[3];  // E_proj       (32,256,256)
    const float* rel = (const float*)d_in[4];  // rel_embedd   (64)
    float* out = (float*)d_out;                // (32,64,64) fp32

    k_stage1<<<512, 64>>>(cp, wc);
    k_stage2<<<128, 256>>>(E);
    k_final<<<32, 256>>>(wn, rel, out);
}